// round 3
// baseline (speedup 1.0000x reference)
#include <cuda_runtime.h>
#include <cuda_bf16.h>
#include <math.h>

// Problem constants
#define T_TOK   8192      // B*S = 4*2048
#define D_DIM   1024
#define H1      128       // hidden
#define HEADS   2
#define K_DIM   16
#define HALF    8
#define N_KEYS  256
#define KNN     8

// Scratch (module-level device globals; no runtime allocation)
__device__ float g_h[T_TOK * H1];          // relu(x@W1^T + b1)
__device__ float g_w[T_TOK * HEADS * KNN]; // softmax weights
__device__ int   g_idx[T_TOK * HEADS * KNN];

// ---------------------------------------------------------------------------
// Kernel 1: h = relu(x @ W1^T + b1).  M=8192, N=128, K=1024.
// BM=64, BN=128, BK=16, 256 threads, 4x8 microtile, double-buffered smem.
// Grid = 128 blocks.
// ---------------------------------------------------------------------------
#define BM 64
#define BN 128
#define BK 16
#define LDA 68   // 64+4 pad, keeps 16B alignment
#define LDB 132  // 128+4 pad

__global__ __launch_bounds__(256) void gemm1_kernel(
    const float* __restrict__ x,
    const float* __restrict__ W1,
    const float* __restrict__ b1)
{
    __shared__ float As[2][BK][LDA];
    __shared__ float Bs[2][BK][LDB];

    const int tid = threadIdx.x;
    const int tx = tid & 15;        // 0..15 -> col group (8 cols)
    const int ty = tid >> 4;        // 0..15 -> row group (4 rows)

    // Global load indexing
    const int arow = tid >> 2;            // 0..63
    const int ac   = (tid & 3) * 4;       // 0,4,8,12
    const int brow = tid >> 2;            // 0..63 (and +64)
    const int bc   = (tid & 3) * 4;

    const float* xg  = x  + ((size_t)(blockIdx.x * BM + arow)) * D_DIM + ac;
    const float* wg0 = W1 + (size_t)brow        * D_DIM + bc;
    const float* wg1 = W1 + (size_t)(brow + 64) * D_DIM + bc;

    float acc[4][8];
#pragma unroll
    for (int i = 0; i < 4; i++)
#pragma unroll
        for (int j = 0; j < 8; j++) acc[i][j] = 0.f;

    const int ntiles = D_DIM / BK;  // 64

    // Preload tile 0
    float4 aR = *(const float4*)(xg);
    float4 bR0 = *(const float4*)(wg0);
    float4 bR1 = *(const float4*)(wg1);
    {
        As[0][ac + 0][arow] = aR.x;
        As[0][ac + 1][arow] = aR.y;
        As[0][ac + 2][arow] = aR.z;
        As[0][ac + 3][arow] = aR.w;
        Bs[0][bc + 0][brow] = bR0.x;
        Bs[0][bc + 1][brow] = bR0.y;
        Bs[0][bc + 2][brow] = bR0.z;
        Bs[0][bc + 3][brow] = bR0.w;
        Bs[0][bc + 0][brow + 64] = bR1.x;
        Bs[0][bc + 1][brow + 64] = bR1.y;
        Bs[0][bc + 2][brow + 64] = bR1.z;
        Bs[0][bc + 3][brow + 64] = bR1.w;
    }
    __syncthreads();

    for (int t = 0; t < ntiles; t++) {
        const int cur = t & 1;
        const int nxt = cur ^ 1;

        if (t + 1 < ntiles) {
            const int ko = (t + 1) * BK;
            aR  = *(const float4*)(xg  + ko);
            bR0 = *(const float4*)(wg0 + ko);
            bR1 = *(const float4*)(wg1 + ko);
        }

#pragma unroll
        for (int kk = 0; kk < BK; kk++) {
            float4 av  = *(const float4*)&As[cur][kk][ty * 4];
            float4 b0v = *(const float4*)&Bs[cur][kk][tx * 8];
            float4 b1v = *(const float4*)&Bs[cur][kk][tx * 8 + 4];
            float a_[4] = {av.x, av.y, av.z, av.w};
            float b_[8] = {b0v.x, b0v.y, b0v.z, b0v.w, b1v.x, b1v.y, b1v.z, b1v.w};
#pragma unroll
            for (int i = 0; i < 4; i++)
#pragma unroll
                for (int j = 0; j < 8; j++)
                    acc[i][j] = fmaf(a_[i], b_[j], acc[i][j]);
        }

        if (t + 1 < ntiles) {
            As[nxt][ac + 0][arow] = aR.x;
            As[nxt][ac + 1][arow] = aR.y;
            As[nxt][ac + 2][arow] = aR.z;
            As[nxt][ac + 3][arow] = aR.w;
            Bs[nxt][bc + 0][brow] = bR0.x;
            Bs[nxt][bc + 1][brow] = bR0.y;
            Bs[nxt][bc + 2][brow] = bR0.z;
            Bs[nxt][bc + 3][brow] = bR0.w;
            Bs[nxt][bc + 0][brow + 64] = bR1.x;
            Bs[nxt][bc + 1][brow + 64] = bR1.y;
            Bs[nxt][bc + 2][brow + 64] = bR1.z;
            Bs[nxt][bc + 3][brow + 64] = bR1.w;
        }
        __syncthreads();
    }

    // Epilogue: + b1, relu, store
    const int mbase = blockIdx.x * BM + ty * 4;
    const int nbase = tx * 8;
    float bb[8];
#pragma unroll
    for (int j = 0; j < 8; j++) bb[j] = b1[nbase + j];

#pragma unroll
    for (int i = 0; i < 4; i++) {
        float4 o0, o1;
        o0.x = fmaxf(acc[i][0] + bb[0], 0.f);
        o0.y = fmaxf(acc[i][1] + bb[1], 0.f);
        o0.z = fmaxf(acc[i][2] + bb[2], 0.f);
        o0.w = fmaxf(acc[i][3] + bb[3], 0.f);
        o1.x = fmaxf(acc[i][4] + bb[4], 0.f);
        o1.y = fmaxf(acc[i][5] + bb[5], 0.f);
        o1.z = fmaxf(acc[i][6] + bb[6], 0.f);
        o1.w = fmaxf(acc[i][7] + bb[7], 0.f);
        float* op = g_h + (size_t)(mbase + i) * H1 + nbase;
        *(float4*)op       = o0;
        *(float4*)(op + 4) = o1;
    }
}

// ---------------------------------------------------------------------------
// Kernel 2: per token: q = h@W2^T + b2, scores vs keys, per-half top-8,
// 8x8 combine top-8, softmax -> (w, idx).  One warp per token, 8 tokens/block.
// ---------------------------------------------------------------------------
__device__ __forceinline__ unsigned long long pack_vi(float v, int i) {
    unsigned u = __float_as_uint(v);
    u = (u & 0x80000000u) ? ~u : (u | 0x80000000u);  // monotonic map
    return ((unsigned long long)u << 32) | (unsigned)i;
}
__device__ __forceinline__ float unpack_v(unsigned long long p) {
    unsigned u = (unsigned)(p >> 32);
    u = (u & 0x80000000u) ? (u ^ 0x80000000u) : ~u;
    return __uint_as_float(u);
}

__global__ __launch_bounds__(256) void topk_kernel(
    const float* __restrict__ W2,
    const float* __restrict__ b2,
    const float* __restrict__ keys)
{
    __shared__ float W2t[H1 * 32];    // transposed: W2t[c*32 + j] = W2[j][c]
    __shared__ float hs[8][H1];
    __shared__ float qs[8][32];
    __shared__ float sc1s[8][8];
    __shared__ float sc2s[8][8];
    __shared__ int   i1s[8][8];
    __shared__ int   i2s[8][8];

    const int tid  = threadIdx.x;
    const int w    = tid >> 5;
    const int lane = tid & 31;
    const int t    = blockIdx.x * 8 + w;

    // cooperative W2 transpose into smem (coalesced global reads)
    for (int i = tid; i < 32 * H1; i += 256) {
        int j = i >> 7;       // 0..31  (output dim)
        int c = i & 127;      // 0..127 (hidden dim)
        W2t[c * 32 + j] = W2[i];
    }
    __syncthreads();

    // load h row (32 lanes x float4 = 128 floats)
    {
        float4 hv = ((const float4*)(g_h + (size_t)t * H1))[lane];
        ((float4*)hs[w])[lane] = hv;
    }
    __syncwarp();

    // q[lane] = b2[lane] + sum_c hs[c] * W2t[c*32+lane]
    {
        float acc = b2[lane];
#pragma unroll 8
        for (int c = 0; c < H1; c++)
            acc = fmaf(hs[w][c], W2t[c * 32 + lane], acc);
        qs[w][lane] = acc;
    }
    __syncwarp();

    for (int hd = 0; hd < HEADS; hd++) {
        // ---- per-half scores + top-8 ----
        for (int half = 0; half < 2; half++) {
            float q0[8];
#pragma unroll
            for (int c = 0; c < 8; c++) q0[c] = qs[w][hd * K_DIM + half * HALF + c];

            float s[8];
            const float* kb = keys + (size_t)((hd * 2 + half) * N_KEYS) * HALF;
#pragma unroll
            for (int r = 0; r < 8; r++) {
                const int n = r * 32 + lane;
                const float4 ka = *(const float4*)(kb + (size_t)n * HALF);
                const float4 kc = *(const float4*)(kb + (size_t)n * HALF + 4);
                float v = q0[0] * ka.x + q0[1] * ka.y + q0[2] * ka.z + q0[3] * ka.w
                        + q0[4] * kc.x + q0[5] * kc.y + q0[6] * kc.z + q0[7] * kc.w;
                s[r] = v;
            }

            float* sc_sm = half ? sc2s[w] : sc1s[w];
            int*   ix_sm = half ? i2s[w]  : i1s[w];
            unsigned taken = 0;
#pragma unroll
            for (int k = 0; k < 8; k++) {
                float best = -3e38f; int br = 0;
#pragma unroll
                for (int r = 0; r < 8; r++) {
                    bool ok = !((taken >> r) & 1u);
                    if (ok && s[r] > best) { best = s[r]; br = r; }
                }
                unsigned long long p = pack_vi(best, br * 32 + lane);
#pragma unroll
                for (int off = 16; off; off >>= 1) {
                    unsigned long long o = __shfl_xor_sync(0xffffffffu, p, off);
                    if (o > p) p = o;
                }
                int n = (int)(p & 0xffffffffu);
                if (lane == 0) { sc_sm[k] = unpack_v(p); ix_sm[k] = n; }
                if ((n & 31) == lane) taken |= 1u << (n >> 5);
            }
            __syncwarp();
        }

        // ---- combine 8x8 -> top-8 ----
        const float a0 = sc1s[w][lane >> 3];
        const float a1 = sc1s[w][(lane >> 3) + 4];
        const float bsc = sc2s[w][lane & 7];
        float v0 = a0 + bsc;
        float v1 = a1 + bsc;

        float scf[8];
        int   idxk[8];
        unsigned tk = 0;
#pragma unroll
        for (int k = 0; k < 8; k++) {
            float best = -3e38f;
            int bc = lane;
            if (!(tk & 1u) && v0 > best) { best = v0; bc = lane; }
            if (!(tk & 2u) && v1 > best) { best = v1; bc = lane + 32; }
            unsigned long long p = pack_vi(best, bc);
#pragma unroll
            for (int off = 16; off; off >>= 1) {
                unsigned long long o = __shfl_xor_sync(0xffffffffu, p, off);
                if (o > p) p = o;
            }
            const int cc = (int)(p & 0xffffffffu);
            scf[k]  = unpack_v(p);
            idxk[k] = i1s[w][cc >> 3] * N_KEYS + i2s[w][cc & 7];
            if (cc == lane)      tk |= 1u;
            if (cc == lane + 32) tk |= 2u;
        }

        // ---- softmax over the 8 selected (scf[0] is the max) ----
        const float m0 = scf[0];
        float ek[8];
        float sum = 0.f;
#pragma unroll
        for (int k = 0; k < 8; k++) { ek[k] = expf(scf[k] - m0); sum += ek[k]; }

        float myv = ek[0];
        int   myi = idxk[0];
#pragma unroll
        for (int k = 1; k < 8; k++)
            if (lane == k) { myv = ek[k]; myi = idxk[k]; }

        if (lane < 8) {
            g_w[(size_t)(t * HEADS + hd) * KNN + lane]   = myv / sum;
            g_idx[(size_t)(t * HEADS + hd) * KNN + lane] = myi;
        }
        __syncwarp();
    }
}

// ---------------------------------------------------------------------------
// Kernel 3: out[t,:] = sum_{i<16} w_i * values[idx_i, :].  One block/token.
// ---------------------------------------------------------------------------
__global__ __launch_bounds__(256) void gather_kernel(
    const float* __restrict__ values,
    float* __restrict__ out)
{
    const int t = blockIdx.x;
    __shared__ float ws[16];
    __shared__ int   is[16];
    if (threadIdx.x < 16) {
        ws[threadIdx.x] = g_w[(size_t)t * 16 + threadIdx.x];
        is[threadIdx.x] = g_idx[(size_t)t * 16 + threadIdx.x];
    }
    __syncthreads();

    const int d = threadIdx.x;  // float4 column, 0..255
    const float4* v4 = (const float4*)values;
    float4 acc = make_float4(0.f, 0.f, 0.f, 0.f);
#pragma unroll
    for (int i = 0; i < 16; i++) {
        const float4 v = __ldg(v4 + (size_t)is[i] * 256 + d);
        const float wi = ws[i];
        acc.x = fmaf(wi, v.x, acc.x);
        acc.y = fmaf(wi, v.y, acc.y);
        acc.z = fmaf(wi, v.z, acc.z);
        acc.w = fmaf(wi, v.w, acc.w);
    }
    ((float4*)out)[(size_t)t * 256 + d] = acc;
}

// ---------------------------------------------------------------------------
extern "C" void kernel_launch(void* const* d_in, const int* in_sizes, int n_in,
                              void* d_out, int out_size)
{
    const float* x      = (const float*)d_in[0];
    const float* W1     = (const float*)d_in[1];
    const float* b1     = (const float*)d_in[2];
    const float* W2     = (const float*)d_in[3];
    const float* b2     = (const float*)d_in[4];
    const float* keys   = (const float*)d_in[5];
    const float* values = (const float*)d_in[6];
    float* out          = (float*)d_out;

    gemm1_kernel<<<T_TOK / BM, 256>>>(x, W1, b1);
    topk_kernel<<<T_TOK / 8, 256>>>(W2, b2, keys);
    gather_kernel<<<T_TOK, 256>>>(values, out);
}